// round 1
// baseline (speedup 1.0000x reference)
#include <cuda_runtime.h>
#include <math.h>

// Problem constants
#define BATCH 2
#define SQ    2048
#define DM    2048     // model dim
#define KVD   512      // G*HD
#define NH    32       // heads
#define NG    8        // kv groups
#define HDIM  64       // head dim

// Scratch (allocation-free rule: __device__ globals)
__device__ float g_Q[(size_t)BATCH * SQ * DM];   // 33.5 MB
__device__ float g_K[(size_t)BATCH * SQ * KVD];  // 8.4 MB
__device__ float g_V[(size_t)BATCH * SQ * KVD];  // 8.4 MB
__device__ float g_C[(size_t)BATCH * SQ * DM];   // 33.5 MB

// ---------------------------------------------------------------------------
// SGEMM: C[M,N] = A[M,K] * W[N,K]^T   (both operands K-contiguous, "NT")
// 128x128 tile, BK=16, 256 threads, 8x8 per thread.
// asel: 0 -> use Aext, 1 -> use g_C
// csel: 0 -> g_Q, 1 -> g_K, 2 -> g_V, 3 -> Cext
// ---------------------------------------------------------------------------
#define BM 128
#define BN 128
#define BK 16

__global__ __launch_bounds__(256) void sgemm_nt(
    const float* __restrict__ Aext, const float* __restrict__ W,
    float* __restrict__ Cext, int asel, int csel, int M, int N, int K)
{
    const float* A = (asel == 1) ? g_C : Aext;
    float* C = (csel == 0) ? g_Q : (csel == 1) ? g_K : (csel == 2) ? g_V : Cext;

    __shared__ float As[BK][BM + 4];   // [k][m], padded rows (528B, 16B-aligned)
    __shared__ float Bs[BK][BN + 4];   // [k][n]

    const int tid = threadIdx.x;
    const int m0 = blockIdx.y * BM;
    const int n0 = blockIdx.x * BN;
    const int tx = tid & 15;           // 16 cols of threads
    const int ty = tid >> 4;           // 16 rows of threads

    float acc[8][8];
#pragma unroll
    for (int i = 0; i < 8; i++)
#pragma unroll
        for (int j = 0; j < 8; j++) acc[i][j] = 0.f;

    for (int k0 = 0; k0 < K; k0 += BK) {
#pragma unroll
        for (int t = 0; t < 2; t++) {
            int f = tid + t * 256;          // 0..511
            int row = f >> 2;               // 0..127
            int c4 = (f & 3) * 4;           // 0,4,8,12
            float4 va = *(const float4*)&A[(size_t)(m0 + row) * K + k0 + c4];
            As[c4 + 0][row] = va.x; As[c4 + 1][row] = va.y;
            As[c4 + 2][row] = va.z; As[c4 + 3][row] = va.w;
            float4 vb = *(const float4*)&W[(size_t)(n0 + row) * K + k0 + c4];
            Bs[c4 + 0][row] = vb.x; Bs[c4 + 1][row] = vb.y;
            Bs[c4 + 2][row] = vb.z; Bs[c4 + 3][row] = vb.w;
        }
        __syncthreads();

#pragma unroll
        for (int k = 0; k < BK; k++) {
            float ra[8], rb[8];
            *(float4*)&ra[0] = *(const float4*)&As[k][ty * 8];
            *(float4*)&ra[4] = *(const float4*)&As[k][ty * 8 + 4];
            *(float4*)&rb[0] = *(const float4*)&Bs[k][tx * 8];
            *(float4*)&rb[4] = *(const float4*)&Bs[k][tx * 8 + 4];
#pragma unroll
            for (int i = 0; i < 8; i++)
#pragma unroll
                for (int j = 0; j < 8; j++) acc[i][j] += ra[i] * rb[j];
        }
        __syncthreads();
    }

#pragma unroll
    for (int i = 0; i < 8; i++) {
        size_t r = (size_t)(m0 + ty * 8 + i) * N + n0 + tx * 8;
        *(float4*)&C[r]     = make_float4(acc[i][0], acc[i][1], acc[i][2], acc[i][3]);
        *(float4*)&C[r + 4] = make_float4(acc[i][4], acc[i][5], acc[i][6], acc[i][7]);
    }
}

// ---------------------------------------------------------------------------
// Causal GQA flash attention (fp32).
// Grid: (32 q-tiles, B*H). CTA: 256 threads. BQ=64, BKV=32, HD=64.
// Online softmax; per-CTA Q tile resident in smem (transposed, pre-scaled).
// ---------------------------------------------------------------------------
__global__ __launch_bounds__(256) void gqa_attn()
{
    __shared__ float Qt[64][64];       // [d][q], scaled by 1/8
    __shared__ float Kt[64][36];       // [d][k]
    __shared__ float Vs[32][68];       // [k][d]
    __shared__ float Pt[32][68];       // [k][q] scores -> probs
    __shared__ float m_s[64], l_s[64], a_s[64];

    const int tid = threadIdx.x;
    const int qt = blockIdx.x;
    const int bh = blockIdx.y;
    const int b = bh >> 5;
    const int h = bh & 31;
    const int g = h >> 2;              // GS = 4
    const int q0 = qt * 64;
    const float scale = 0.125f;        // 1/sqrt(64)

    const float* Qbase = g_Q + (size_t)b * SQ * DM + h * HDIM;
    const float* Kbase = g_K + (size_t)b * SQ * KVD + g * HDIM;
    const float* Vbase = g_V + (size_t)b * SQ * KVD + g * HDIM;

    // Load Q tile transposed + pre-scaled (once per CTA)
    for (int idx = tid; idx < 64 * 64; idx += 256) {
        int qq = idx >> 6, d = idx & 63;
        Qt[d][qq] = Qbase[(size_t)(q0 + qq) * DM + d] * scale;
    }
    if (tid < 64) { m_s[tid] = -1e30f; l_s[tid] = 0.f; }

    const int tx = tid & 15;           // 16 threads over k/d cols
    const int ty = tid >> 4;           // 16 threads over q rows
    float o[4][4];
#pragma unroll
    for (int i = 0; i < 4; i++)
#pragma unroll
        for (int j = 0; j < 4; j++) o[i][j] = 0.f;

    const int nkt = qt * 2 + 2;        // kv tiles with k0 <= q0+63

    for (int kt = 0; kt < nkt; kt++) {
        const int k0 = kt * 32;
        __syncthreads();   // protect Kt/Vs/Pt reuse; first iter: Qt/m/l visible

        for (int idx = tid; idx < 32 * 64; idx += 256) {
            int kk = idx >> 6, d = idx & 63;
            Kt[d][kk] = Kbase[(size_t)(k0 + kk) * KVD + d];
        }
        for (int idx = tid; idx < 32 * 64; idx += 256) {
            int kk = idx >> 6, d = idx & 63;
            Vs[kk][d] = Vbase[(size_t)(k0 + kk) * KVD + d];
        }
        __syncthreads();

        // S = (Q*scale) . K^T   -> frag 4q x 2k per thread
        float s[4][2] = {{0.f,0.f},{0.f,0.f},{0.f,0.f},{0.f,0.f}};
#pragma unroll 16
        for (int d = 0; d < 64; d++) {
            float4 ra = *(const float4*)&Qt[d][ty * 4];
            float2 rb = *(const float2*)&Kt[d][tx * 2];
            s[0][0] += ra.x * rb.x;  s[0][1] += ra.x * rb.y;
            s[1][0] += ra.y * rb.x;  s[1][1] += ra.y * rb.y;
            s[2][0] += ra.z * rb.x;  s[2][1] += ra.z * rb.y;
            s[3][0] += ra.w * rb.x;  s[3][1] += ra.w * rb.y;
        }
        // causal mask + write raw scores into Pt[k][q]
#pragma unroll
        for (int i = 0; i < 4; i++) {
            int qq = q0 + ty * 4 + i;
#pragma unroll
            for (int j = 0; j < 2; j++) {
                int kk = k0 + tx * 2 + j;
                Pt[tx * 2 + j][ty * 4 + i] = (kk <= qq) ? s[i][j] : -1e30f;
            }
        }
        __syncthreads();

        // Per-row online softmax (one thread per q row)
        if (tid < 64) {
            float mold = m_s[tid];
            float mx = mold;
#pragma unroll
            for (int kk = 0; kk < 32; kk++) mx = fmaxf(mx, Pt[kk][tid]);
            float alpha = __expf(mold - mx);
            float sum = 0.f;
#pragma unroll
            for (int kk = 0; kk < 32; kk++) {
                float p = __expf(Pt[kk][tid] - mx);
                Pt[kk][tid] = p;
                sum += p;
            }
            m_s[tid] = mx;
            l_s[tid] = l_s[tid] * alpha + sum;
            a_s[tid] = alpha;
        }
        __syncthreads();

        // Rescale accumulators + P.V  -> frag 4q x 4d per thread
        float al[4];
#pragma unroll
        for (int i = 0; i < 4; i++) al[i] = a_s[ty * 4 + i];
#pragma unroll
        for (int i = 0; i < 4; i++)
#pragma unroll
            for (int j = 0; j < 4; j++) o[i][j] *= al[i];

#pragma unroll
        for (int kk = 0; kk < 32; kk++) {
            float4 rp = *(const float4*)&Pt[kk][ty * 4];
            float4 rv = *(const float4*)&Vs[kk][tx * 4];
            o[0][0] += rp.x * rv.x; o[0][1] += rp.x * rv.y; o[0][2] += rp.x * rv.z; o[0][3] += rp.x * rv.w;
            o[1][0] += rp.y * rv.x; o[1][1] += rp.y * rv.y; o[1][2] += rp.y * rv.z; o[1][3] += rp.y * rv.w;
            o[2][0] += rp.z * rv.x; o[2][1] += rp.z * rv.y; o[2][2] += rp.z * rv.z; o[2][3] += rp.z * rv.w;
            o[3][0] += rp.w * rv.x; o[3][1] += rp.w * rv.y; o[3][2] += rp.w * rv.z; o[3][3] += rp.w * rv.w;
        }
    }

    // Epilogue: ctx[b, q0+qq, h*64 + d] = o / l
#pragma unroll
    for (int i = 0; i < 4; i++) {
        int qq = q0 + ty * 4 + i;
        float inv = 1.f / l_s[ty * 4 + i];
        float4 r = make_float4(o[i][0] * inv, o[i][1] * inv, o[i][2] * inv, o[i][3] * inv);
        *(float4*)&g_C[((size_t)b * SQ + qq) * DM + h * HDIM + tx * 4] = r;
    }
}

// ---------------------------------------------------------------------------
extern "C" void kernel_launch(void* const* d_in, const int* in_sizes, int n_in,
                              void* d_out, int out_size)
{
    (void)in_sizes; (void)n_in; (void)out_size;
    const float* x  = (const float*)d_in[0];
    const float* Wq = (const float*)d_in[1];
    const float* Wk = (const float*)d_in[2];
    const float* Wv = (const float*)d_in[3];
    const float* Wo = (const float*)d_in[4];
    float* out = (float*)d_out;

    const int M = BATCH * SQ;   // 4096
    dim3 thr(256);

    // Q = x @ Wq^T
    sgemm_nt<<<dim3(DM / BN, M / BM), thr>>>(x, Wq, nullptr, 0, 0, M, DM, DM);
    // K = x @ Wk^T
    sgemm_nt<<<dim3(KVD / BN, M / BM), thr>>>(x, Wk, nullptr, 0, 1, M, KVD, DM);
    // V = x @ Wv^T
    sgemm_nt<<<dim3(KVD / BN, M / BM), thr>>>(x, Wv, nullptr, 0, 2, M, KVD, DM);
    // Causal GQA attention -> g_C
    gqa_attn<<<dim3(SQ / 64, BATCH * NH), thr>>>();
    // out = ctx @ Wo^T
    sgemm_nt<<<dim3(DM / BN, M / BM), thr>>>(nullptr, Wo, out, 1, 3, M, DM, DM);
}

// round 3
// speedup vs baseline: 1.7364x; 1.7364x over previous
#include <cuda_runtime.h>
#include <math.h>
#include <stdint.h>

// Problem constants
#define BATCH 2
#define SQ    2048
#define DM    2048     // model dim
#define KVD   512      // G*HD
#define NH    32       // heads
#define HDIM  64       // head dim

// Scratch (allocation-free rule: __device__ globals)
__device__ float g_Q[(size_t)BATCH * SQ * DM];   // 33.5 MB
__device__ float g_K[(size_t)BATCH * SQ * KVD];  // 8.4 MB
__device__ float g_V[(size_t)BATCH * SQ * KVD];  // 8.4 MB
__device__ float g_C[(size_t)BATCH * SQ * DM];   // 33.5 MB

// ---------------------------------------------------------------------------
// helpers
// ---------------------------------------------------------------------------
__device__ __forceinline__ uint32_t smem_u32(const void* p) {
    uint32_t a;
    asm("{ .reg .u64 t; cvta.to.shared.u64 t, %1; cvt.u32.u64 %0, t; }"
        : "=r"(a) : "l"(p));
    return a;
}
__device__ __forceinline__ void cp_async16(uint32_t dst, const void* src) {
    asm volatile("cp.async.cg.shared.global [%0], [%1], 16;" :: "r"(dst), "l"(src));
}
__device__ __forceinline__ void cp_commit() {
    asm volatile("cp.async.commit_group;" ::: "memory");
}
template <int N>
__device__ __forceinline__ void cp_wait() {
    asm volatile("cp.async.wait_group %0;" :: "n"(N) : "memory");
}
__device__ __forceinline__ uint32_t f2tf32(float f) {
    uint32_t r;
    asm("cvt.rna.tf32.f32 %0, %1;" : "=r"(r) : "f"(f));
    return r;
}
__device__ __forceinline__ void mma_tf32(float* c, const uint32_t* a, const uint32_t* b) {
    asm volatile(
        "mma.sync.aligned.m16n8k8.row.col.f32.tf32.tf32.f32 "
        "{%0,%1,%2,%3}, {%4,%5,%6,%7}, {%8,%9}, {%0,%1,%2,%3};"
        : "+f"(c[0]), "+f"(c[1]), "+f"(c[2]), "+f"(c[3])
        : "r"(a[0]), "r"(a[1]), "r"(a[2]), "r"(a[3]), "r"(b[0]), "r"(b[1]));
}

// ---------------------------------------------------------------------------
// TF32 mma.sync GEMM:  C[M,N] = A[M,K] . W[N,K]^T   (both K-contiguous)
// CTA: 128x128 tile, BK=32, 256 threads (8 warps, 2m x 4n; warp tile 64x32).
// cp.async double-buffered smem, padded row stride 36 floats.
// ---------------------------------------------------------------------------
#define ASTRIDE 36
#define STG_FLT (2 * 128 * ASTRIDE)         // floats per stage (A + B)
#define GEMM_SMEM (2 * STG_FLT * 4)         // 73728 bytes

__global__ __launch_bounds__(256) void gemm_tc32(
    const float* __restrict__ Aext, const float* __restrict__ W,
    float* __restrict__ Cext, int asel, int csel, int M, int N, int K)
{
    extern __shared__ float sm[];
    const uint32_t sb = smem_u32(sm);
    const float* A = asel ? g_C : Aext;
    float* C = (csel == 0) ? g_Q : (csel == 1) ? g_K : (csel == 2) ? g_V : Cext;

    const int tid = threadIdx.x;
    const int wid = tid >> 5;
    const int lane = tid & 31;
    const int m0 = blockIdx.y * 128;
    const int n0 = blockIdx.x * 128;
    const int wm0 = (wid >> 2) * 64;        // warp m-origin in tile
    const int wn0 = (wid & 3) * 32;         // warp n-origin in tile

    // cp.async indexing: 1024 16B-chunks per operand per stage, 4 per thread
    const int ld_row = tid >> 1;                  // handled rows: tid/2 + {0,64}... (see loop)
    (void)ld_row;

    float c[4][4][4];
#pragma unroll
    for (int mt = 0; mt < 4; mt++)
#pragma unroll
        for (int nt = 0; nt < 4; nt++)
#pragma unroll
            for (int i = 0; i < 4; i++) c[mt][nt][i] = 0.f;

    const int nk = K / 32;

    // issue stage `kt` into buffer kt&1
    auto issue = [&](int kt) {
        const int buf = kt & 1;
        const uint32_t abase = sb + buf * STG_FLT * 4;
        const uint32_t bbase = abase + 128 * ASTRIDE * 4;
        const int k0 = kt * 32;
#pragma unroll
        for (int i = 0; i < 4; i++) {
            int idx = tid + i * 256;              // 0..1023
            int row = idx >> 3;                   // 0..127
            int ch = idx & 7;                     // 16B chunk within row
            cp_async16(abase + (row * ASTRIDE + ch * 4) * 4,
                       &A[(size_t)(m0 + row) * K + k0 + ch * 4]);
            cp_async16(bbase + (row * ASTRIDE + ch * 4) * 4,
                       &W[(size_t)(n0 + row) * K + k0 + ch * 4]);
        }
        cp_commit();
    };

    issue(0);

    for (int kt = 0; kt < nk; kt++) {
        if (kt + 1 < nk) {
            issue(kt + 1);
            cp_wait<1>();
        } else {
            cp_wait<0>();
        }
        __syncthreads();

        const int buf = kt & 1;
        const float* As = sm + buf * STG_FLT;
        const float* Bs = As + 128 * ASTRIDE;

#pragma unroll
        for (int ks = 0; ks < 4; ks++) {
            const int kk = ks * 8 + (lane & 3);
            uint32_t a[4][4], b[4][2];
            const float* ap = As + (wm0 + (lane >> 2)) * ASTRIDE + kk;
#pragma unroll
            for (int mt = 0; mt < 4; mt++) {
                const float* p = ap + mt * 16 * ASTRIDE;
                a[mt][0] = f2tf32(p[0]);
                a[mt][1] = f2tf32(p[8 * ASTRIDE]);
                a[mt][2] = f2tf32(p[4]);
                a[mt][3] = f2tf32(p[8 * ASTRIDE + 4]);
            }
            const float* bp = Bs + (wn0 + (lane >> 2)) * ASTRIDE + kk;
#pragma unroll
            for (int nt = 0; nt < 4; nt++) {
                b[nt][0] = f2tf32(bp[nt * 8 * ASTRIDE]);
                b[nt][1] = f2tf32(bp[nt * 8 * ASTRIDE + 4]);
            }
#pragma unroll
            for (int mt = 0; mt < 4; mt++)
#pragma unroll
                for (int nt = 0; nt < 4; nt++)
                    mma_tf32(c[mt][nt], a[mt], b[nt]);
        }
        __syncthreads();
    }

    // Epilogue: direct fp32 stores (float2 per fragment half)
#pragma unroll
    for (int mt = 0; mt < 4; mt++) {
        const int r0 = m0 + wm0 + mt * 16 + (lane >> 2);
#pragma unroll
        for (int nt = 0; nt < 4; nt++) {
            const int col = n0 + wn0 + nt * 8 + (lane & 3) * 2;
            *(float2*)&C[(size_t)r0 * N + col] = make_float2(c[mt][nt][0], c[mt][nt][1]);
            *(float2*)&C[(size_t)(r0 + 8) * N + col] = make_float2(c[mt][nt][2], c[mt][nt][3]);
        }
    }
}

// ---------------------------------------------------------------------------
// Causal GQA flash attention (fp32) — unchanged from round 1 (passing).
// ---------------------------------------------------------------------------
__global__ __launch_bounds__(256) void gqa_attn()
{
    __shared__ float Qt[64][64];
    __shared__ float Kt[64][36];
    __shared__ float Vs[32][68];
    __shared__ float Pt[32][68];
    __shared__ float m_s[64], l_s[64], a_s[64];

    const int tid = threadIdx.x;
    const int qt = blockIdx.x;
    const int bh = blockIdx.y;
    const int b = bh >> 5;
    const int h = bh & 31;
    const int g = h >> 2;
    const int q0 = qt * 64;
    const float scale = 0.125f;

    const float* Qbase = g_Q + (size_t)b * SQ * DM + h * HDIM;
    const float* Kbase = g_K + (size_t)b * SQ * KVD + g * HDIM;
    const float* Vbase = g_V + (size_t)b * SQ * KVD + g * HDIM;

    for (int idx = tid; idx < 64 * 64; idx += 256) {
        int qq = idx >> 6, d = idx & 63;
        Qt[d][qq] = Qbase[(size_t)(q0 + qq) * DM + d] * scale;
    }
    if (tid < 64) { m_s[tid] = -1e30f; l_s[tid] = 0.f; }

    const int tx = tid & 15;
    const int ty = tid >> 4;
    float o[4][4];
#pragma unroll
    for (int i = 0; i < 4; i++)
#pragma unroll
        for (int j = 0; j < 4; j++) o[i][j] = 0.f;

    const int nkt = qt * 2 + 2;

    for (int kt = 0; kt < nkt; kt++) {
        const int k0 = kt * 32;
        __syncthreads();

        for (int idx = tid; idx < 32 * 64; idx += 256) {
            int kk = idx >> 6, d = idx & 63;
            Kt[d][kk] = Kbase[(size_t)(k0 + kk) * KVD + d];
        }
        for (int idx = tid; idx < 32 * 64; idx += 256) {
            int kk = idx >> 6, d = idx & 63;
            Vs[kk][d] = Vbase[(size_t)(k0 + kk) * KVD + d];
        }
        __syncthreads();

        float s[4][2] = {{0.f,0.f},{0.f,0.f},{0.f,0.f},{0.f,0.f}};
#pragma unroll 16
        for (int d = 0; d < 64; d++) {
            float4 ra = *(const float4*)&Qt[d][ty * 4];
            float2 rb = *(const float2*)&Kt[d][tx * 2];
            s[0][0] += ra.x * rb.x;  s[0][1] += ra.x * rb.y;
            s[1][0] += ra.y * rb.x;  s[1][1] += ra.y * rb.y;
            s[2][0] += ra.z * rb.x;  s[2][1] += ra.z * rb.y;
            s[3][0] += ra.w * rb.x;  s[3][1] += ra.w * rb.y;
        }
#pragma unroll
        for (int i = 0; i < 4; i++) {
            int qq = q0 + ty * 4 + i;
#pragma unroll
            for (int j = 0; j < 2; j++) {
                int kk = k0 + tx * 2 + j;
                Pt[tx * 2 + j][ty * 4 + i] = (kk <= qq) ? s[i][j] : -1e30f;
            }
        }
        __syncthreads();

        if (tid < 64) {
            float mold = m_s[tid];
            float mx = mold;
#pragma unroll
            for (int kk = 0; kk < 32; kk++) mx = fmaxf(mx, Pt[kk][tid]);
            float alpha = __expf(mold - mx);
            float sum = 0.f;
#pragma unroll
            for (int kk = 0; kk < 32; kk++) {
                float p = __expf(Pt[kk][tid] - mx);
                Pt[kk][tid] = p;
                sum += p;
            }
            m_s[tid] = mx;
            l_s[tid] = l_s[tid] * alpha + sum;
            a_s[tid] = alpha;
        }
        __syncthreads();

        float al[4];
#pragma unroll
        for (int i = 0; i < 4; i++) al[i] = a_s[ty * 4 + i];
#pragma unroll
        for (int i = 0; i < 4; i++)
#pragma unroll
            for (int j = 0; j < 4; j++) o[i][j] *= al[i];

#pragma unroll
        for (int kk = 0; kk < 32; kk++) {
            float4 rp = *(const float4*)&Pt[kk][ty * 4];
            float4 rv = *(const float4*)&Vs[kk][tx * 4];
            o[0][0] += rp.x * rv.x; o[0][1] += rp.x * rv.y; o[0][2] += rp.x * rv.z; o[0][3] += rp.x * rv.w;
            o[1][0] += rp.y * rv.x; o[1][1] += rp.y * rv.y; o[1][2] += rp.y * rv.z; o[1][3] += rp.y * rv.w;
            o[2][0] += rp.z * rv.x; o[2][1] += rp.z * rv.y; o[2][2] += rp.z * rv.z; o[2][3] += rp.z * rv.w;
            o[3][0] += rp.w * rv.x; o[3][1] += rp.w * rv.y; o[3][2] += rp.w * rv.z; o[3][3] += rp.w * rv.w;
        }
    }

#pragma unroll
    for (int i = 0; i < 4; i++) {
        int qq = q0 + ty * 4 + i;
        float inv = 1.f / l_s[ty * 4 + i];
        float4 r = make_float4(o[i][0] * inv, o[i][1] * inv, o[i][2] * inv, o[i][3] * inv);
        *(float4*)&g_C[((size_t)b * SQ + qq) * DM + h * HDIM + tx * 4] = r;
    }
}

// ---------------------------------------------------------------------------
extern "C" void kernel_launch(void* const* d_in, const int* in_sizes, int n_in,
                              void* d_out, int out_size)
{
    (void)in_sizes; (void)n_in; (void)out_size;
    const float* x  = (const float*)d_in[0];
    const float* Wq = (const float*)d_in[1];
    const float* Wk = (const float*)d_in[2];
    const float* Wv = (const float*)d_in[3];
    const float* Wo = (const float*)d_in[4];
    float* out = (float*)d_out;

    const int M = BATCH * SQ;   // 4096
    dim3 thr(256);

    cudaFuncSetAttribute(gemm_tc32, cudaFuncAttributeMaxDynamicSharedMemorySize, GEMM_SMEM);

    // Q = x @ Wq^T
    gemm_tc32<<<dim3(DM / 128, M / 128), thr, GEMM_SMEM>>>(x, Wq, nullptr, 0, 0, M, DM, DM);
    // K = x @ Wk^T
    gemm_tc32<<<dim3(KVD / 128, M / 128), thr, GEMM_SMEM>>>(x, Wk, nullptr, 0, 1, M, KVD, DM);
    // V = x @ Wv^T
    gemm_tc32<<<dim3(KVD / 128, M / 128), thr, GEMM_SMEM>>>(x, Wv, nullptr, 0, 2, M, KVD, DM);
    // Causal GQA attention -> g_C
    gqa_attn<<<dim3(SQ / 64, BATCH * NH), thr>>>();
    // out = ctx @ Wo^T
    gemm_tc32<<<dim3(DM / 128, M / 128), thr, GEMM_SMEM>>>(nullptr, Wo, out, 1, 3, M, DM, DM);
}

// round 4
// speedup vs baseline: 2.5377x; 1.4614x over previous
#include <cuda_runtime.h>
#include <math.h>
#include <stdint.h>

// Problem constants
#define BATCH 2
#define SQ    2048
#define DM    2048     // model dim
#define KVD   512      // G*HD
#define NH    32       // heads
#define HDIM  64       // head dim

// Scratch (allocation-free rule: __device__ globals)
__device__ float g_Q[(size_t)BATCH * SQ * DM];   // 33.5 MB
__device__ float g_K[(size_t)BATCH * SQ * KVD];  // 8.4 MB
__device__ float g_V[(size_t)BATCH * SQ * KVD];  // 8.4 MB
__device__ float g_C[(size_t)BATCH * SQ * DM];   // 33.5 MB

// ---------------------------------------------------------------------------
// helpers
// ---------------------------------------------------------------------------
__device__ __forceinline__ uint32_t smem_u32(const void* p) {
    uint32_t a;
    asm("{ .reg .u64 t; cvta.to.shared.u64 t, %1; cvt.u32.u64 %0, t; }"
        : "=r"(a) : "l"(p));
    return a;
}
__device__ __forceinline__ void cp_async16(uint32_t dst, const void* src) {
    asm volatile("cp.async.cg.shared.global [%0], [%1], 16;" :: "r"(dst), "l"(src));
}
__device__ __forceinline__ void cp_commit() {
    asm volatile("cp.async.commit_group;" ::: "memory");
}
template <int N>
__device__ __forceinline__ void cp_wait() {
    asm volatile("cp.async.wait_group %0;" :: "n"(N) : "memory");
}
__device__ __forceinline__ uint32_t f2tf32(float f) {
    uint32_t r;
    asm("cvt.rna.tf32.f32 %0, %1;" : "=r"(r) : "f"(f));
    return r;
}
__device__ __forceinline__ float f2tf32f(float f) {
    return __uint_as_float(f2tf32(f));
}
__device__ __forceinline__ void mma_tf32(float* c, const uint32_t* a, const uint32_t* b) {
    asm volatile(
        "mma.sync.aligned.m16n8k8.row.col.f32.tf32.tf32.f32 "
        "{%0,%1,%2,%3}, {%4,%5,%6,%7}, {%8,%9}, {%0,%1,%2,%3};"
        : "+f"(c[0]), "+f"(c[1]), "+f"(c[2]), "+f"(c[3])
        : "r"(a[0]), "r"(a[1]), "r"(a[2]), "r"(a[3]), "r"(b[0]), "r"(b[1]));
}

// ---------------------------------------------------------------------------
// TF32 mma.sync GEMM:  C[M,N] = A[M,K] . W[N,K]^T   (both K-contiguous)
// CTA: 128x128 tile, BK=32, 256 threads (8 warps, 2m x 4n; warp tile 64x32).
// cp.async double-buffered smem; per-stage in-place fp32->tf32 pass so the
// MMA loop does plain LDS (no CVT).
// ---------------------------------------------------------------------------
#define ASTRIDE 36
#define STG_FLT (2 * 128 * ASTRIDE)         // floats per stage (A + B) = 9216
#define GEMM_SMEM (2 * STG_FLT * 4)         // 73728 bytes

__global__ __launch_bounds__(256) void gemm_tc32(
    const float* __restrict__ Aext, const float* __restrict__ W,
    float* __restrict__ Cext, int asel, int csel, int M, int N, int K)
{
    extern __shared__ float sm[];
    const uint32_t sb = smem_u32(sm);
    const float* A = asel ? g_C : Aext;
    float* C = (csel == 0) ? g_Q : (csel == 1) ? g_K : (csel == 2) ? g_V : Cext;

    const int tid = threadIdx.x;
    const int wid = tid >> 5;
    const int lane = tid & 31;
    const int m0 = blockIdx.y * 128;
    const int n0 = blockIdx.x * 128;
    const int wm0 = (wid >> 2) * 64;
    const int wn0 = (wid & 3) * 32;

    float c[4][4][4];
#pragma unroll
    for (int mt = 0; mt < 4; mt++)
#pragma unroll
        for (int nt = 0; nt < 4; nt++)
#pragma unroll
            for (int i = 0; i < 4; i++) c[mt][nt][i] = 0.f;

    const int nk = K / 32;

    auto issue = [&](int kt) {
        const int buf = kt & 1;
        const uint32_t abase = sb + buf * STG_FLT * 4;
        const uint32_t bbase = abase + 128 * ASTRIDE * 4;
        const int k0 = kt * 32;
#pragma unroll
        for (int i = 0; i < 4; i++) {
            int idx = tid + i * 256;
            int row = idx >> 3;
            int ch = idx & 7;
            cp_async16(abase + (row * ASTRIDE + ch * 4) * 4,
                       &A[(size_t)(m0 + row) * K + k0 + ch * 4]);
            cp_async16(bbase + (row * ASTRIDE + ch * 4) * 4,
                       &W[(size_t)(n0 + row) * K + k0 + ch * 4]);
        }
        cp_commit();
    };

    issue(0);

    for (int kt = 0; kt < nk; kt++) {
        if (kt + 1 < nk) {
            issue(kt + 1);
            cp_wait<1>();
        } else {
            cp_wait<0>();
        }
        __syncthreads();

        const int buf = kt & 1;
        float* st = sm + buf * STG_FLT;

        // in-place fp32 -> tf32 (covers A+B incl. pads; 9216 floats = 2304 f4)
#pragma unroll
        for (int i = 0; i < 9; i++) {
            float4* p = (float4*)st + tid + i * 256;
            float4 v = *p;
            *p = make_float4(f2tf32f(v.x), f2tf32f(v.y), f2tf32f(v.z), f2tf32f(v.w));
        }
        __syncthreads();

        const float* As = st;
        const float* Bs = As + 128 * ASTRIDE;

#pragma unroll
        for (int ks = 0; ks < 4; ks++) {
            const int kk = ks * 8 + (lane & 3);
            uint32_t a[4][4], b[4][2];
            const float* ap = As + (wm0 + (lane >> 2)) * ASTRIDE + kk;
#pragma unroll
            for (int mt = 0; mt < 4; mt++) {
                const float* p = ap + mt * 16 * ASTRIDE;
                a[mt][0] = __float_as_uint(p[0]);
                a[mt][1] = __float_as_uint(p[8 * ASTRIDE]);
                a[mt][2] = __float_as_uint(p[4]);
                a[mt][3] = __float_as_uint(p[8 * ASTRIDE + 4]);
            }
            const float* bp = Bs + (wn0 + (lane >> 2)) * ASTRIDE + kk;
#pragma unroll
            for (int nt = 0; nt < 4; nt++) {
                b[nt][0] = __float_as_uint(bp[nt * 8 * ASTRIDE]);
                b[nt][1] = __float_as_uint(bp[nt * 8 * ASTRIDE + 4]);
            }
#pragma unroll
            for (int mt = 0; mt < 4; mt++)
#pragma unroll
                for (int nt = 0; nt < 4; nt++)
                    mma_tf32(c[mt][nt], a[mt], b[nt]);
        }
        __syncthreads();
    }

#pragma unroll
    for (int mt = 0; mt < 4; mt++) {
        const int r0 = m0 + wm0 + mt * 16 + (lane >> 2);
#pragma unroll
        for (int nt = 0; nt < 4; nt++) {
            const int col = n0 + wn0 + nt * 8 + (lane & 3) * 2;
            *(float2*)&C[(size_t)r0 * N + col] = make_float2(c[mt][nt][0], c[mt][nt][1]);
            *(float2*)&C[(size_t)(r0 + 8) * N + col] = make_float2(c[mt][nt][2], c[mt][nt][3]);
        }
    }
}

// ---------------------------------------------------------------------------
// Tensor-core causal GQA flash attention (tf32 mma, fp32 softmax).
// CTA: (qt, b*32+h); 256 threads = 8 warps; BQ=128 (16 q-rows/warp), BKV=64.
// smem: Ks[64][68] (XOR-swizzled), Vt[64][68] (V transposed, swizzled),
//       Pt[128][68] (Q staging, then P round-trip; per-warp region).
// ---------------------------------------------------------------------------
#define PAD 68
#define ATTN_SMEM ((64 * PAD + 64 * PAD + 128 * PAD) * 4)   // 69632 B

__global__ __launch_bounds__(256) void gqa_attn_tc()
{
    extern __shared__ float asm_[];
    float* Ks = asm_;                 // [64][PAD]
    float* Vt = Ks + 64 * PAD;        // [64][PAD]
    float* Pt = Vt + 64 * PAD;        // [128][PAD]

    const int tid = threadIdx.x;
    const int w = tid >> 5;
    const int lane = tid & 31;
    const int r = lane >> 2;          // 0..7
    const int cb = lane & 3;          // 0..3
    const int qt = blockIdx.x;
    const int bh = blockIdx.y;
    const int b = bh >> 5, h = bh & 31, g = h >> 2;
    const int q0 = qt * 128;
    const int wrow = w * 16;
    const int sw = (r & 3) << 3;      // frag-read column swizzle

    const float* Qb = g_Q + (size_t)b * SQ * DM + h * HDIM;
    const float* Kb = g_K + (size_t)b * SQ * KVD + g * HDIM;
    const float* Vb = g_V + (size_t)b * SQ * KVD + g * HDIM;

    // Stage Q (scaled by 1/8, tf32-rounded) into Pt
#pragma unroll
    for (int i = 0; i < 8; i++) {
        int idx = tid + i * 256;            // 128 rows x 16 chunks
        int row = idx >> 4, ch = idx & 15;
        float4 v = *(const float4*)&Qb[(size_t)(q0 + row) * DM + ch * 4];
        float* dst = &Pt[row * PAD + ch * 4];
        dst[0] = f2tf32f(v.x * 0.125f);
        dst[1] = f2tf32f(v.y * 0.125f);
        dst[2] = f2tf32f(v.z * 0.125f);
        dst[3] = f2tf32f(v.w * 0.125f);
    }
    __syncthreads();

    uint32_t qf[8][4];
#pragma unroll
    for (int ks = 0; ks < 8; ks++) {
        qf[ks][0] = __float_as_uint(Pt[(wrow + r) * PAD + ks * 8 + cb]);
        qf[ks][1] = __float_as_uint(Pt[(wrow + 8 + r) * PAD + ks * 8 + cb]);
        qf[ks][2] = __float_as_uint(Pt[(wrow + r) * PAD + ks * 8 + cb + 4]);
        qf[ks][3] = __float_as_uint(Pt[(wrow + 8 + r) * PAD + ks * 8 + cb + 4]);
    }
    __syncthreads();

    float of[8][4];
#pragma unroll
    for (int dt = 0; dt < 8; dt++)
#pragma unroll
        for (int i = 0; i < 4; i++) of[dt][i] = 0.f;
    float m0r = -1e30f, m1r = -1e30f, l0 = 0.f, l1 = 0.f;

    const int nkt = qt * 2 + 2;

    for (int kt = 0; kt < nkt; kt++) {
        const int k0 = kt * 64;
        __syncthreads();   // protect Ks/Vt reuse

        // K tile: coalesced, column XOR-swizzle per row quad, tf32
#pragma unroll
        for (int i = 0; i < 4; i++) {
            int idx = tid + i * 256;
            int kk = idx >> 4, ch = idx & 15;
            float4 v = *(const float4*)&Kb[(size_t)(k0 + kk) * KVD + ch * 4];
            float* dst = &Ks[kk * PAD + ((ch * 4) ^ ((kk & 3) << 3))];
            dst[0] = f2tf32f(v.x); dst[1] = f2tf32f(v.y);
            dst[2] = f2tf32f(v.z); dst[3] = f2tf32f(v.w);
        }
        // V tile, transposed: lane -> (kk = (tid&15)+16i, d0 = (tid>>4)*4)
#pragma unroll
        for (int i = 0; i < 4; i++) {
            int kk = (tid & 15) + 16 * i;
            int d0 = (tid >> 4) * 4;
            float4 v = *(const float4*)&Vb[(size_t)(k0 + kk) * KVD + d0];
            Vt[(d0 + 0) * PAD + (kk ^ 0)]  = f2tf32f(v.x);
            Vt[(d0 + 1) * PAD + (kk ^ 8)]  = f2tf32f(v.y);
            Vt[(d0 + 2) * PAD + (kk ^ 16)] = f2tf32f(v.z);
            Vt[(d0 + 3) * PAD + (kk ^ 24)] = f2tf32f(v.w);
        }
        __syncthreads();

        const bool active = (k0 <= q0 + wrow + 15);
        if (active) {
            // S = Q.K^T
            float sf[8][4];
#pragma unroll
            for (int nt = 0; nt < 8; nt++)
#pragma unroll
                for (int i = 0; i < 4; i++) sf[nt][i] = 0.f;
#pragma unroll
            for (int ks = 0; ks < 8; ks++) {
                const int c = ((ks * 8 + cb) ^ sw);
#pragma unroll
                for (int nt = 0; nt < 8; nt++) {
                    const float* kp = &Ks[(nt * 8 + r) * PAD + c];
                    uint32_t bb[2] = { __float_as_uint(kp[0]), __float_as_uint(kp[4]) };
                    mma_tf32(sf[nt], qf[ks], bb);
                }
            }
            // causal mask (only diagonal-crossing tiles need it)
            if (k0 + 63 > q0 + wrow) {
                const int qr0 = q0 + wrow + r;
                const int qr1 = qr0 + 8;
#pragma unroll
                for (int nt = 0; nt < 8; nt++) {
                    const int kvc = k0 + nt * 8 + cb * 2;
                    if (kvc > qr0)     sf[nt][0] = -1e30f;
                    if (kvc + 1 > qr0) sf[nt][1] = -1e30f;
                    if (kvc > qr1)     sf[nt][2] = -1e30f;
                    if (kvc + 1 > qr1) sf[nt][3] = -1e30f;
                }
            }
            // online softmax
            float mx0 = m0r, mx1 = m1r;
#pragma unroll
            for (int nt = 0; nt < 8; nt++) {
                mx0 = fmaxf(mx0, fmaxf(sf[nt][0], sf[nt][1]));
                mx1 = fmaxf(mx1, fmaxf(sf[nt][2], sf[nt][3]));
            }
            mx0 = fmaxf(mx0, __shfl_xor_sync(0xffffffffu, mx0, 1));
            mx0 = fmaxf(mx0, __shfl_xor_sync(0xffffffffu, mx0, 2));
            mx1 = fmaxf(mx1, __shfl_xor_sync(0xffffffffu, mx1, 1));
            mx1 = fmaxf(mx1, __shfl_xor_sync(0xffffffffu, mx1, 2));
            const float a0 = __expf(m0r - mx0), a1 = __expf(m1r - mx1);
            m0r = mx0; m1r = mx1;
            float s0 = 0.f, s1 = 0.f;
#pragma unroll
            for (int nt = 0; nt < 8; nt++) {
                float p00 = __expf(sf[nt][0] - mx0);
                float p01 = __expf(sf[nt][1] - mx0);
                float p10 = __expf(sf[nt][2] - mx1);
                float p11 = __expf(sf[nt][3] - mx1);
                s0 += p00 + p01; s1 += p10 + p11;
                *(float2*)&Pt[(wrow + r) * PAD + nt * 8 + cb * 2] =
                    make_float2(f2tf32f(p00), f2tf32f(p01));
                *(float2*)&Pt[(wrow + 8 + r) * PAD + nt * 8 + cb * 2] =
                    make_float2(f2tf32f(p10), f2tf32f(p11));
            }
            s0 += __shfl_xor_sync(0xffffffffu, s0, 1);
            s0 += __shfl_xor_sync(0xffffffffu, s0, 2);
            s1 += __shfl_xor_sync(0xffffffffu, s1, 1);
            s1 += __shfl_xor_sync(0xffffffffu, s1, 2);
            l0 = l0 * a0 + s0;
            l1 = l1 * a1 + s1;
#pragma unroll
            for (int dt = 0; dt < 8; dt++) {
                of[dt][0] *= a0; of[dt][1] *= a0;
                of[dt][2] *= a1; of[dt][3] *= a1;
            }
            __syncwarp();
            // O += P.V
#pragma unroll
            for (int ks = 0; ks < 8; ks++) {
                uint32_t a[4];
                a[0] = __float_as_uint(Pt[(wrow + r) * PAD + ks * 8 + cb]);
                a[1] = __float_as_uint(Pt[(wrow + 8 + r) * PAD + ks * 8 + cb]);
                a[2] = __float_as_uint(Pt[(wrow + r) * PAD + ks * 8 + cb + 4]);
                a[3] = __float_as_uint(Pt[(wrow + 8 + r) * PAD + ks * 8 + cb + 4]);
                const int c = ((ks * 8 + cb) ^ sw);
#pragma unroll
                for (int dt = 0; dt < 8; dt++) {
                    const float* vp = &Vt[(dt * 8 + r) * PAD + c];
                    uint32_t bb[2] = { __float_as_uint(vp[0]), __float_as_uint(vp[4]) };
                    mma_tf32(of[dt], a, bb);
                }
            }
        }
    }

    // epilogue
    const float i0 = 1.f / l0, i1 = 1.f / l1;
    float* C0 = g_C + ((size_t)b * SQ + q0 + wrow + r) * DM + h * HDIM;
    float* C1 = C0 + 8 * DM;
#pragma unroll
    for (int dt = 0; dt < 8; dt++) {
        const int col = dt * 8 + cb * 2;
        *(float2*)&C0[col] = make_float2(of[dt][0] * i0, of[dt][1] * i0);
        *(float2*)&C1[col] = make_float2(of[dt][2] * i1, of[dt][3] * i1);
    }
}

// ---------------------------------------------------------------------------
extern "C" void kernel_launch(void* const* d_in, const int* in_sizes, int n_in,
                              void* d_out, int out_size)
{
    (void)in_sizes; (void)n_in; (void)out_size;
    const float* x  = (const float*)d_in[0];
    const float* Wq = (const float*)d_in[1];
    const float* Wk = (const float*)d_in[2];
    const float* Wv = (const float*)d_in[3];
    const float* Wo = (const float*)d_in[4];
    float* out = (float*)d_out;

    const int M = BATCH * SQ;   // 4096
    dim3 thr(256);

    cudaFuncSetAttribute(gemm_tc32, cudaFuncAttributeMaxDynamicSharedMemorySize, GEMM_SMEM);
    cudaFuncSetAttribute(gqa_attn_tc, cudaFuncAttributeMaxDynamicSharedMemorySize, ATTN_SMEM);

    // Q = x @ Wq^T
    gemm_tc32<<<dim3(DM / 128, M / 128), thr, GEMM_SMEM>>>(x, Wq, nullptr, 0, 0, M, DM, DM);
    // K = x @ Wk^T
    gemm_tc32<<<dim3(KVD / 128, M / 128), thr, GEMM_SMEM>>>(x, Wk, nullptr, 0, 1, M, KVD, DM);
    // V = x @ Wv^T
    gemm_tc32<<<dim3(KVD / 128, M / 128), thr, GEMM_SMEM>>>(x, Wv, nullptr, 0, 2, M, KVD, DM);
    // Causal GQA attention -> g_C
    gqa_attn_tc<<<dim3(SQ / 128, BATCH * NH), thr, ATTN_SMEM>>>();
    // out = ctx @ Wo^T
    gemm_tc32<<<dim3(DM / 128, M / 128), thr, GEMM_SMEM>>>(nullptr, Wo, out, 1, 3, M, DM, DM);
}

// round 5
// speedup vs baseline: 3.3056x; 1.3026x over previous
#include <cuda_runtime.h>
#include <math.h>
#include <stdint.h>

// Problem constants
#define BATCH 2
#define SQ    2048
#define DM    2048     // model dim
#define KVD   512      // G*HD
#define NH    32       // heads
#define HDIM  64       // head dim

// Scratch (allocation-free rule: __device__ globals)
__device__ float g_Q[(size_t)BATCH * SQ * DM];   // 33.5 MB
__device__ float g_K[(size_t)BATCH * SQ * KVD];  // 8.4 MB
__device__ float g_V[(size_t)BATCH * SQ * KVD];  // 8.4 MB
__device__ float g_C[(size_t)BATCH * SQ * DM];   // 33.5 MB (ctx, tf32-rounded)
__device__ float g_Xt[(size_t)BATCH * SQ * DM];  // 33.5 MB (x, tf32-rounded)
// packed tf32 weights: Wq | Wk | Wv | Wo
#define WQ_OFF 0
#define WK_OFF (2048 * 2048)
#define WV_OFF (WK_OFF + 512 * 2048)
#define WO_OFF (WV_OFF + 512 * 2048)
__device__ float g_Wt[WO_OFF + 2048 * 2048];     // 42 MB

// ---------------------------------------------------------------------------
// helpers
// ---------------------------------------------------------------------------
__device__ __forceinline__ uint32_t smem_u32(const void* p) {
    uint32_t a;
    asm("{ .reg .u64 t; cvta.to.shared.u64 t, %1; cvt.u32.u64 %0, t; }"
        : "=r"(a) : "l"(p));
    return a;
}
__device__ __forceinline__ void cp_async16(uint32_t dst, const void* src) {
    asm volatile("cp.async.cg.shared.global [%0], [%1], 16;" :: "r"(dst), "l"(src));
}
__device__ __forceinline__ void cp_commit() {
    asm volatile("cp.async.commit_group;" ::: "memory");
}
template <int N>
__device__ __forceinline__ void cp_wait() {
    asm volatile("cp.async.wait_group %0;" :: "n"(N) : "memory");
}
__device__ __forceinline__ uint32_t f2tf32(float f) {
    uint32_t r;
    asm("cvt.rna.tf32.f32 %0, %1;" : "=r"(r) : "f"(f));
    return r;
}
__device__ __forceinline__ float f2tf32f(float f) {
    return __uint_as_float(f2tf32(f));
}
__device__ __forceinline__ void mma_tf32(float* c, const uint32_t* a, const uint32_t* b) {
    asm volatile(
        "mma.sync.aligned.m16n8k8.row.col.f32.tf32.tf32.f32 "
        "{%0,%1,%2,%3}, {%4,%5,%6,%7}, {%8,%9}, {%0,%1,%2,%3};"
        : "+f"(c[0]), "+f"(c[1]), "+f"(c[2]), "+f"(c[3])
        : "r"(a[0]), "r"(a[1]), "r"(a[2]), "r"(a[3]), "r"(b[0]), "r"(b[1]));
}

// ---------------------------------------------------------------------------
// One-shot fp32 -> tf32-bits conversion (bandwidth kernel)
// ---------------------------------------------------------------------------
__global__ __launch_bounds__(256) void cvt_tf32_k(const float4* __restrict__ src,
                                                  float4* __restrict__ dst, int n4)
{
    int i = blockIdx.x * 256 + threadIdx.x;
    if (i < n4) {
        float4 v = src[i];
        dst[i] = make_float4(f2tf32f(v.x), f2tf32f(v.y), f2tf32f(v.z), f2tf32f(v.w));
    }
}

// ---------------------------------------------------------------------------
// TF32 mma.sync GEMM on pre-converted data:  C[M,N] = A[M,K] . W[N,K]^T
// CTA: 128x128 tile, BK=32, 256 threads (8 warps, 2m x 4n; warp tile 64x32).
// cp.async double-buffered smem; no in-loop conversion.
// ---------------------------------------------------------------------------
#define ASTRIDE 36
#define STG_FLT (2 * 128 * ASTRIDE)         // floats per stage (A + B) = 9216
#define GEMM_SMEM (2 * STG_FLT * 4)         // 73728 bytes

__global__ __launch_bounds__(256, 2) void gemm_tc32(
    int asel, int woff, int csel, float* __restrict__ Cext,
    int M, int N, int K)
{
    extern __shared__ float sm[];
    const uint32_t sb = smem_u32(sm);
    const float* A = asel ? g_C : g_Xt;
    const float* W = g_Wt + woff;
    float* C = (csel == 0) ? g_Q : (csel == 1) ? g_K : (csel == 2) ? g_V : Cext;

    const int tid = threadIdx.x;
    const int wid = tid >> 5;
    const int lane = tid & 31;
    const int m0 = blockIdx.y * 128;
    const int n0 = blockIdx.x * 128;
    const int wm0 = (wid >> 2) * 64;
    const int wn0 = (wid & 3) * 32;

    float c[4][4][4];
#pragma unroll
    for (int mt = 0; mt < 4; mt++)
#pragma unroll
        for (int nt = 0; nt < 4; nt++)
#pragma unroll
            for (int i = 0; i < 4; i++) c[mt][nt][i] = 0.f;

    const int nk = K / 32;

    auto issue = [&](int kt) {
        const int buf = kt & 1;
        const uint32_t abase = sb + buf * STG_FLT * 4;
        const uint32_t bbase = abase + 128 * ASTRIDE * 4;
        const int k0 = kt * 32;
#pragma unroll
        for (int i = 0; i < 4; i++) {
            int idx = tid + i * 256;
            int row = idx >> 3;
            int ch = idx & 7;
            cp_async16(abase + (row * ASTRIDE + ch * 4) * 4,
                       &A[(size_t)(m0 + row) * K + k0 + ch * 4]);
            cp_async16(bbase + (row * ASTRIDE + ch * 4) * 4,
                       &W[(size_t)(n0 + row) * K + k0 + ch * 4]);
        }
        cp_commit();
    };

    issue(0);

    for (int kt = 0; kt < nk; kt++) {
        if (kt + 1 < nk) {
            issue(kt + 1);
            cp_wait<1>();
        } else {
            cp_wait<0>();
        }
        __syncthreads();

        const float* As = sm + (kt & 1) * STG_FLT;
        const float* Bs = As + 128 * ASTRIDE;

#pragma unroll
        for (int ks = 0; ks < 4; ks++) {
            const int kk = ks * 8 + (lane & 3);
            uint32_t a[4][4], b[4][2];
            const float* ap = As + (wm0 + (lane >> 2)) * ASTRIDE + kk;
#pragma unroll
            for (int mt = 0; mt < 4; mt++) {
                const float* p = ap + mt * 16 * ASTRIDE;
                a[mt][0] = __float_as_uint(p[0]);
                a[mt][1] = __float_as_uint(p[8 * ASTRIDE]);
                a[mt][2] = __float_as_uint(p[4]);
                a[mt][3] = __float_as_uint(p[8 * ASTRIDE + 4]);
            }
            const float* bp = Bs + (wn0 + (lane >> 2)) * ASTRIDE + kk;
#pragma unroll
            for (int nt = 0; nt < 4; nt++) {
                b[nt][0] = __float_as_uint(bp[nt * 8 * ASTRIDE]);
                b[nt][1] = __float_as_uint(bp[nt * 8 * ASTRIDE + 4]);
            }
#pragma unroll
            for (int mt = 0; mt < 4; mt++)
#pragma unroll
                for (int nt = 0; nt < 4; nt++)
                    mma_tf32(c[mt][nt], a[mt], b[nt]);
        }
        __syncthreads();
    }

#pragma unroll
    for (int mt = 0; mt < 4; mt++) {
        const int r0 = m0 + wm0 + mt * 16 + (lane >> 2);
#pragma unroll
        for (int nt = 0; nt < 4; nt++) {
            const int col = n0 + wn0 + nt * 8 + (lane & 3) * 2;
            *(float2*)&C[(size_t)r0 * N + col] = make_float2(c[mt][nt][0], c[mt][nt][1]);
            *(float2*)&C[(size_t)(r0 + 8) * N + col] = make_float2(c[mt][nt][2], c[mt][nt][3]);
        }
    }
}

// ---------------------------------------------------------------------------
// Tensor-core causal GQA flash attention (tf32 mma, fp32 softmax).
// CTA: (qt, b*32+h); 256 threads = 8 warps; BQ=128 (16 q-rows/warp), BKV=64.
// ---------------------------------------------------------------------------
#define PAD 68
#define ATTN_SMEM ((64 * PAD + 64 * PAD + 128 * PAD) * 4)   // 69632 B

__global__ __launch_bounds__(256, 2) void gqa_attn_tc()
{
    extern __shared__ float asm_[];
    float* Ks = asm_;                 // [64][PAD]
    float* Vt = Ks + 64 * PAD;        // [64][PAD]
    float* Pt = Vt + 64 * PAD;        // [128][PAD]

    const int tid = threadIdx.x;
    const int w = tid >> 5;
    const int lane = tid & 31;
    const int r = lane >> 2;
    const int cb = lane & 3;
    const int qt = blockIdx.x;
    const int bh = blockIdx.y;
    const int b = bh >> 5, h = bh & 31, g = h >> 2;
    const int q0 = qt * 128;
    const int wrow = w * 16;
    const int sw = (r & 3) << 3;

    const float* Qb = g_Q + (size_t)b * SQ * DM + h * HDIM;
    const float* Kb = g_K + (size_t)b * SQ * KVD + g * HDIM;
    const float* Vb = g_V + (size_t)b * SQ * KVD + g * HDIM;

    // Stage Q (scaled by 1/8, tf32-rounded) into Pt
#pragma unroll
    for (int i = 0; i < 8; i++) {
        int idx = tid + i * 256;
        int row = idx >> 4, ch = idx & 15;
        float4 v = *(const float4*)&Qb[(size_t)(q0 + row) * DM + ch * 4];
        float* dst = &Pt[row * PAD + ch * 4];
        dst[0] = f2tf32f(v.x * 0.125f);
        dst[1] = f2tf32f(v.y * 0.125f);
        dst[2] = f2tf32f(v.z * 0.125f);
        dst[3] = f2tf32f(v.w * 0.125f);
    }
    __syncthreads();

    uint32_t qf[8][4];
#pragma unroll
    for (int ks = 0; ks < 8; ks++) {
        qf[ks][0] = __float_as_uint(Pt[(wrow + r) * PAD + ks * 8 + cb]);
        qf[ks][1] = __float_as_uint(Pt[(wrow + 8 + r) * PAD + ks * 8 + cb]);
        qf[ks][2] = __float_as_uint(Pt[(wrow + r) * PAD + ks * 8 + cb + 4]);
        qf[ks][3] = __float_as_uint(Pt[(wrow + 8 + r) * PAD + ks * 8 + cb + 4]);
    }
    __syncthreads();

    float of[8][4];
#pragma unroll
    for (int dt = 0; dt < 8; dt++)
#pragma unroll
        for (int i = 0; i < 4; i++) of[dt][i] = 0.f;
    float m0r = -1e30f, m1r = -1e30f, l0 = 0.f, l1 = 0.f;

    const int nkt = qt * 2 + 2;

    for (int kt = 0; kt < nkt; kt++) {
        const int k0 = kt * 64;
        __syncthreads();

#pragma unroll
        for (int i = 0; i < 4; i++) {
            int idx = tid + i * 256;
            int kk = idx >> 4, ch = idx & 15;
            float4 v = *(const float4*)&Kb[(size_t)(k0 + kk) * KVD + ch * 4];
            float* dst = &Ks[kk * PAD + ((ch * 4) ^ ((kk & 3) << 3))];
            dst[0] = f2tf32f(v.x); dst[1] = f2tf32f(v.y);
            dst[2] = f2tf32f(v.z); dst[3] = f2tf32f(v.w);
        }
#pragma unroll
        for (int i = 0; i < 4; i++) {
            int kk = (tid & 15) + 16 * i;
            int d0 = (tid >> 4) * 4;
            float4 v = *(const float4*)&Vb[(size_t)(k0 + kk) * KVD + d0];
            Vt[(d0 + 0) * PAD + (kk ^ 0)]  = f2tf32f(v.x);
            Vt[(d0 + 1) * PAD + (kk ^ 8)]  = f2tf32f(v.y);
            Vt[(d0 + 2) * PAD + (kk ^ 16)] = f2tf32f(v.z);
            Vt[(d0 + 3) * PAD + (kk ^ 24)] = f2tf32f(v.w);
        }
        __syncthreads();

        const bool active = (k0 <= q0 + wrow + 15);
        if (active) {
            float sf[8][4];
#pragma unroll
            for (int nt = 0; nt < 8; nt++)
#pragma unroll
                for (int i = 0; i < 4; i++) sf[nt][i] = 0.f;
#pragma unroll
            for (int ks = 0; ks < 8; ks++) {
                const int c = ((ks * 8 + cb) ^ sw);
#pragma unroll
                for (int nt = 0; nt < 8; nt++) {
                    const float* kp = &Ks[(nt * 8 + r) * PAD + c];
                    uint32_t bb[2] = { __float_as_uint(kp[0]), __float_as_uint(kp[4]) };
                    mma_tf32(sf[nt], qf[ks], bb);
                }
            }
            if (k0 + 63 > q0 + wrow) {
                const int qr0 = q0 + wrow + r;
                const int qr1 = qr0 + 8;
#pragma unroll
                for (int nt = 0; nt < 8; nt++) {
                    const int kvc = k0 + nt * 8 + cb * 2;
                    if (kvc > qr0)     sf[nt][0] = -1e30f;
                    if (kvc + 1 > qr0) sf[nt][1] = -1e30f;
                    if (kvc > qr1)     sf[nt][2] = -1e30f;
                    if (kvc + 1 > qr1) sf[nt][3] = -1e30f;
                }
            }
            float mx0 = m0r, mx1 = m1r;
#pragma unroll
            for (int nt = 0; nt < 8; nt++) {
                mx0 = fmaxf(mx0, fmaxf(sf[nt][0], sf[nt][1]));
                mx1 = fmaxf(mx1, fmaxf(sf[nt][2], sf[nt][3]));
            }
            mx0 = fmaxf(mx0, __shfl_xor_sync(0xffffffffu, mx0, 1));
            mx0 = fmaxf(mx0, __shfl_xor_sync(0xffffffffu, mx0, 2));
            mx1 = fmaxf(mx1, __shfl_xor_sync(0xffffffffu, mx1, 1));
            mx1 = fmaxf(mx1, __shfl_xor_sync(0xffffffffu, mx1, 2));
            const float a0 = __expf(m0r - mx0), a1 = __expf(m1r - mx1);
            m0r = mx0; m1r = mx1;
            float s0 = 0.f, s1 = 0.f;
#pragma unroll
            for (int nt = 0; nt < 8; nt++) {
                float p00 = __expf(sf[nt][0] - mx0);
                float p01 = __expf(sf[nt][1] - mx0);
                float p10 = __expf(sf[nt][2] - mx1);
                float p11 = __expf(sf[nt][3] - mx1);
                s0 += p00 + p01; s1 += p10 + p11;
                *(float2*)&Pt[(wrow + r) * PAD + nt * 8 + cb * 2] =
                    make_float2(f2tf32f(p00), f2tf32f(p01));
                *(float2*)&Pt[(wrow + 8 + r) * PAD + nt * 8 + cb * 2] =
                    make_float2(f2tf32f(p10), f2tf32f(p11));
            }
            s0 += __shfl_xor_sync(0xffffffffu, s0, 1);
            s0 += __shfl_xor_sync(0xffffffffu, s0, 2);
            s1 += __shfl_xor_sync(0xffffffffu, s1, 1);
            s1 += __shfl_xor_sync(0xffffffffu, s1, 2);
            l0 = l0 * a0 + s0;
            l1 = l1 * a1 + s1;
#pragma unroll
            for (int dt = 0; dt < 8; dt++) {
                of[dt][0] *= a0; of[dt][1] *= a0;
                of[dt][2] *= a1; of[dt][3] *= a1;
            }
            __syncwarp();
#pragma unroll
            for (int ks = 0; ks < 8; ks++) {
                uint32_t a[4];
                a[0] = __float_as_uint(Pt[(wrow + r) * PAD + ks * 8 + cb]);
                a[1] = __float_as_uint(Pt[(wrow + 8 + r) * PAD + ks * 8 + cb]);
                a[2] = __float_as_uint(Pt[(wrow + r) * PAD + ks * 8 + cb + 4]);
                a[3] = __float_as_uint(Pt[(wrow + 8 + r) * PAD + ks * 8 + cb + 4]);
                const int c = ((ks * 8 + cb) ^ sw);
#pragma unroll
                for (int dt = 0; dt < 8; dt++) {
                    const float* vp = &Vt[(dt * 8 + r) * PAD + c];
                    uint32_t bb[2] = { __float_as_uint(vp[0]), __float_as_uint(vp[4]) };
                    mma_tf32(of[dt], a, bb);
                }
            }
        }
    }

    // epilogue: write ctx already tf32-rounded (final GEMM reads it raw)
    const float i0 = 1.f / l0, i1 = 1.f / l1;
    float* C0 = g_C + ((size_t)b * SQ + q0 + wrow + r) * DM + h * HDIM;
    float* C1 = C0 + 8 * DM;
#pragma unroll
    for (int dt = 0; dt < 8; dt++) {
        const int col = dt * 8 + cb * 2;
        *(float2*)&C0[col] = make_float2(f2tf32f(of[dt][0] * i0), f2tf32f(of[dt][1] * i0));
        *(float2*)&C1[col] = make_float2(f2tf32f(of[dt][2] * i1), f2tf32f(of[dt][3] * i1));
    }
}

// ---------------------------------------------------------------------------
extern "C" void kernel_launch(void* const* d_in, const int* in_sizes, int n_in,
                              void* d_out, int out_size)
{
    (void)in_sizes; (void)n_in; (void)out_size;
    const float* x  = (const float*)d_in[0];
    const float* Wq = (const float*)d_in[1];
    const float* Wk = (const float*)d_in[2];
    const float* Wv = (const float*)d_in[3];
    const float* Wo = (const float*)d_in[4];
    float* out = (float*)d_out;

    const int M = BATCH * SQ;   // 4096
    dim3 thr(256);

    cudaFuncSetAttribute(gemm_tc32, cudaFuncAttributeMaxDynamicSharedMemorySize, GEMM_SMEM);
    cudaFuncSetAttribute(gqa_attn_tc, cudaFuncAttributeMaxDynamicSharedMemorySize, ATTN_SMEM);

    float* xt; cudaGetSymbolAddress((void**)&xt, g_Xt);
    float* wt; cudaGetSymbolAddress((void**)&wt, g_Wt);

    // Pre-convert x and weights to tf32 bit patterns (rna, once)
    {
        int n4 = (int)((size_t)M * DM / 4);
        cvt_tf32_k<<<(n4 + 255) / 256, thr>>>((const float4*)x, (float4*)xt, n4);
        n4 = DM * DM / 4;
        cvt_tf32_k<<<(n4 + 255) / 256, thr>>>((const float4*)Wq, (float4*)(wt + WQ_OFF), n4);
        n4 = KVD * DM / 4;
        cvt_tf32_k<<<(n4 + 255) / 256, thr>>>((const float4*)Wk, (float4*)(wt + WK_OFF), n4);
        cvt_tf32_k<<<(n4 + 255) / 256, thr>>>((const float4*)Wv, (float4*)(wt + WV_OFF), n4);
        n4 = DM * DM / 4;
        cvt_tf32_k<<<(n4 + 255) / 256, thr>>>((const float4*)Wo, (float4*)(wt + WO_OFF), n4);
    }

    // Q = x @ Wq^T
    gemm_tc32<<<dim3(DM / 128, M / 128), thr, GEMM_SMEM>>>(0, WQ_OFF, 0, nullptr, M, DM, DM);
    // K = x @ Wk^T
    gemm_tc32<<<dim3(KVD / 128, M / 128), thr, GEMM_SMEM>>>(0, WK_OFF, 1, nullptr, M, KVD, DM);
    // V = x @ Wv^T
    gemm_tc32<<<dim3(KVD / 128, M / 128), thr, GEMM_SMEM>>>(0, WV_OFF, 2, nullptr, M, KVD, DM);
    // Causal GQA attention -> g_C
    gqa_attn_tc<<<dim3(SQ / 128, BATCH * NH), thr, ATTN_SMEM>>>();
    // out = ctx @ Wo^T
    gemm_tc32<<<dim3(DM / 128, M / 128), thr, GEMM_SMEM>>>(1, WO_OFF, 3, out, M, DM, DM);
}